// round 15
// baseline (speedup 1.0000x reference)
#include <cuda_runtime.h>
#include <cuda_fp16.h>
#include <math.h>
#include <stdint.h>

// ============================================================================
// ResponseAttention via mma.sync (m16n8k16 fp16), asymmetric Ozaki split.
//   scores = Qs · K'^T, Qs=(x·Wq^T+bq)/sqrt(H), K'=(x+rp)·Wk^T+2bk
//   out    = softmax(scores) · V   (V stored transposed so P·V is NT too)
// Projections: 2-MMA split on the WEIGHT side only. Big GEMMs: 1-MMA fp16.
// Softmax fused into QK epilogue (exp on FMA pipe, no max pass) + deferred
// row normalization in PV epilogue. rel_err ~5.25e-4.
// R15: BK=64 for the big GEMMs (QK 16->8 iters, PV 128->64) — with only 8
// warps/SM the per-iteration seams (barrier+CP_WAIT+LDSM startup) were the
// exposed cost; halving iteration count amortizes them. 144B row pad keeps
// ldsm conflict-free; 108KB smem still fits 2 CTAs/SM. proj3 stays BK=32
// (3-matrix stage at BK=64 would drop to 1 CTA/SM = R12 failure mode).
// tcgen05 unavailable (compute_103 virtual arch) — mma.sync is the path.
// B=4, S=4096, H=512.
// ============================================================================

#define BM 128
#define BN 128
#define NSTAGE 3
#define NTH 128

#define TOK 16384
#define HD  512
#define SEQ 4096
#define NB  4

// proj smem: rows of 32 fp16 padded to 40 halves (80 B) -> conflict-free ldsm
#define ROWB 80
#define MATB (128 * ROWB)                       // 128x32 fp16 matrix: 10240 B
#define SMEM_PROJ (NSTAGE * 3 * MATB)           // 92160: A BH BL

// big-GEMM smem: rows of 64 fp16 padded to 72 halves (144 B) -> conflict-free
#define ROWB2 144
#define MATB2 (128 * ROWB2)                     // 128x64 fp16 matrix: 18432 B
#define SMEM_BIG (NSTAGE * 2 * MATB2)           // 110592: A BH

#define TSTR 136                                // transpose-buffer row stride (halves)
#define PSCALE 0.0625f                          // P stored as e/16 (overflow headroom)

// ---------------------------- scratch ------------------------------------
__device__ __half g_xsh[TOK * HD];
__device__ __half g_xrh[TOK * HD];
__device__ __half g_wqh[HD * HD], g_wql[HD * HD];
__device__ __half g_wkh[HD * HD], g_wkl[HD * HD];
__device__ __half g_wvh[HD * HD], g_wvl[HD * HD];
__device__ __half g_qh[TOK * HD];
__device__ __half g_kh[TOK * HD];
__device__ __half g_vth[TOK * HD];
__device__ __half g_ph[(size_t)NB * SEQ * SEQ];
__device__ float  g_rs[NB * SEQ];               // softmax row sums (unscaled)

// ---------------------------- helpers ------------------------------------
__device__ __forceinline__ uint32_t smem_u32(const void* p) {
    uint32_t a;
    asm("{ .reg .u64 t; cvta.to.shared.u64 t, %1; cvt.u32.u64 %0, t; }"
        : "=r"(a) : "l"(p));
    return a;
}
__device__ __forceinline__ void cp16(uint32_t s, const void* g) {
    asm volatile("cp.async.cg.shared.global [%0], [%1], 16;" :: "r"(s), "l"(g));
}
#define CP_COMMIT() asm volatile("cp.async.commit_group;")
#define CP_WAIT(n)  asm volatile("cp.async.wait_group %0;" :: "n"(n))

__device__ __forceinline__ void ldsm4(uint32_t r[4], uint32_t addr) {
    asm volatile("ldmatrix.sync.aligned.m8n8.x4.shared.b16 {%0,%1,%2,%3}, [%4];"
        : "=r"(r[0]), "=r"(r[1]), "=r"(r[2]), "=r"(r[3]) : "r"(addr));
}
__device__ __forceinline__ void mma16816(float acc[4], const uint32_t a[4],
                                         const uint32_t b0, const uint32_t b1) {
    asm volatile(
        "mma.sync.aligned.m16n8k16.row.col.f32.f16.f16.f32 "
        "{%0,%1,%2,%3}, {%4,%5,%6,%7}, {%8,%9}, {%0,%1,%2,%3};"
        : "+f"(acc[0]), "+f"(acc[1]), "+f"(acc[2]), "+f"(acc[3])
        : "r"(a[0]), "r"(a[1]), "r"(a[2]), "r"(a[3]), "r"(b0), "r"(b1));
}

// fast exp on FMA/ALU pipes (exp2 magic-round + deg-5 poly, rel err ~2e-6)
__device__ __forceinline__ float fexp(float x) {
    x = fmaxf(x, -87.0f);
    const float t = x * 1.4426950408889634f;
    const float z = t + 12582912.0f;            // 1.5 * 2^23: round to nearest
    const int   n = __float_as_int(z);
    const float f = t - (z - 12582912.0f);
    float p = 1.3333558146e-3f;
    p = fmaf(p, f, 9.6181291076e-3f);
    p = fmaf(p, f, 5.5504108664e-2f);
    p = fmaf(p, f, 2.4022650696e-1f);
    p = fmaf(p, f, 6.9314718056e-1f);
    p = fmaf(p, f, 1.0f);
    return __int_as_float(__float_as_int(p) + (n << 23));
}

// ---------------------------------------------------------------------------
// TileCtx: 4 warps, warp grid 2M x 2N, warp tile 64x64. acc[4][8][4].
// ---------------------------------------------------------------------------
struct TileCtx {
    uint32_t sbase;
    int tid, lane, wid, warpM, warpN;
    int a_row, a_kad, b_row, b_kad;
};

__device__ __forceinline__ TileCtx make_ctx(uint32_t sbase) {
    TileCtx c;
    c.sbase = sbase;
    c.tid  = threadIdx.x;
    c.lane = c.tid & 31;
    c.wid  = c.tid >> 5;
    c.warpM = c.wid & 1;
    c.warpN = c.wid >> 1;             // 0..1
    c.a_row = c.warpM * 64 + (c.lane & 15);
    c.a_kad = (c.lane >> 4) << 3;
    c.b_row = c.warpN * 64 + (c.lane & 7) + ((c.lane >> 4) << 3);
    c.b_kad = ((c.lane >> 3) & 1) << 3;
    return c;
}

// ---------------------------------------------------------------------------
// Projection mainloop (BK=32, B = hi+lo, 2 MMAs per fragment)
// ---------------------------------------------------------------------------
__device__ __forceinline__ void mainloop_proj(
    const TileCtx& c, const __half* AH, const __half* BH, const __half* BL,
    int m0, int n0, int K, float acc[4][8][4])
{
    constexpr int BK = 32;
    constexpr uint32_t ST_BH = MATB;
    constexpr uint32_t ST_BL = 2 * MATB;
    constexpr uint32_t STG   = 3 * MATB;

#pragma unroll
    for (int mi = 0; mi < 4; mi++)
#pragma unroll
        for (int ni = 0; ni < 8; ni++)
#pragma unroll
            for (int r = 0; r < 4; r++) acc[mi][ni][r] = 0.0f;

    auto fill = [&](int stg, int kt) {
        const int kc = kt * BK;
        const uint32_t sb = c.sbase + stg * STG;
#pragma unroll
        for (int j = 0; j < 4; j++) {
            const int idx = c.tid + NTH * j;
            const int r  = idx >> 2;
            const int ch = idx & 3;
            const uint32_t so = (uint32_t)(r * ROWB + ch * 16);
            cp16(sb + so,         AH + (size_t)(m0 + r) * K + kc + ch * 8);
            cp16(sb + ST_BH + so, BH + (size_t)(n0 + r) * K + kc + ch * 8);
            cp16(sb + ST_BL + so, BL + (size_t)(n0 + r) * K + kc + ch * 8);
        }
        CP_COMMIT();
    };

    const int KT = K / BK;
    fill(0, 0);
    fill(1, 1);

    for (int kt = 0; kt < KT; kt++) {
        if (kt == KT - 1) { CP_WAIT(0); } else { CP_WAIT(1); }
        __syncthreads();
        const uint32_t sb = c.sbase + (kt % NSTAGE) * STG;
        if (kt + NSTAGE - 1 < KT) fill((kt + NSTAGE - 1) % NSTAGE, kt + NSTAGE - 1);

#pragma unroll
        for (int ks = 0; ks < 2; ks++) {
            const int ko = ks * 16;
            uint32_t aH[4][4];
#pragma unroll
            for (int mi = 0; mi < 4; mi++) {
                const uint32_t ad = sb
                    + (uint32_t)((c.a_row + mi * 16) * ROWB + (ko + c.a_kad) * 2);
                ldsm4(aH[mi], ad);
            }
            uint32_t bHf[4][4], bLf[4][4];
#pragma unroll
            for (int nf = 0; nf < 4; nf++) {
                const uint32_t bd = sb + ST_BH
                    + (uint32_t)((c.b_row + nf * 16) * ROWB + (ko + c.b_kad) * 2);
                ldsm4(bHf[nf], bd);
                ldsm4(bLf[nf], bd + (ST_BL - ST_BH));
            }
#pragma unroll
            for (int mi = 0; mi < 4; mi++) {
#pragma unroll
                for (int ni = 0; ni < 8; ni++) {
                    const uint32_t* bh = &bHf[ni >> 1][(ni & 1) * 2];
                    const uint32_t* bl = &bLf[ni >> 1][(ni & 1) * 2];
                    mma16816(acc[mi][ni], aH[mi], bh[0], bh[1]);
                    mma16816(acc[mi][ni], aH[mi], bl[0], bl[1]);
                }
            }
        }
    }
}

// ---------------------------------------------------------------------------
// Big-GEMM mainloop (BK=64, B = hi only, 1 MMA per fragment)
// ---------------------------------------------------------------------------
__device__ __forceinline__ void mainloop_big(
    const TileCtx& c, const __half* AH, const __half* BH,
    int m0, int n0, int K, float acc[4][8][4])
{
    constexpr int BK = 64;
    constexpr uint32_t ST_B = MATB2;
    constexpr uint32_t STG  = 2 * MATB2;

#pragma unroll
    for (int mi = 0; mi < 4; mi++)
#pragma unroll
        for (int ni = 0; ni < 8; ni++)
#pragma unroll
            for (int r = 0; r < 4; r++) acc[mi][ni][r] = 0.0f;

    auto fill = [&](int stg, int kt) {
        const int kc = kt * BK;
        const uint32_t sb = c.sbase + stg * STG;
#pragma unroll
        for (int j = 0; j < 8; j++) {
            const int idx = c.tid + NTH * j;   // 0..1023
            const int r  = idx >> 3;
            const int ch = idx & 7;
            const uint32_t so = (uint32_t)(r * ROWB2 + ch * 16);
            cp16(sb + so,        AH + (size_t)(m0 + r) * K + kc + ch * 8);
            cp16(sb + ST_B + so, BH + (size_t)(n0 + r) * K + kc + ch * 8);
        }
        CP_COMMIT();
    };

    const int KT = K / BK;                      // QK: 8, PV: 64
    fill(0, 0);
    fill(1, 1);

    for (int kt = 0; kt < KT; kt++) {
        if (kt == KT - 1) { CP_WAIT(0); } else { CP_WAIT(1); }
        __syncthreads();
        const uint32_t sb = c.sbase + (kt % NSTAGE) * STG;
        if (kt + NSTAGE - 1 < KT) fill((kt + NSTAGE - 1) % NSTAGE, kt + NSTAGE - 1);

#pragma unroll
        for (int ks = 0; ks < 4; ks++) {
            const int ko = ks * 16;
            uint32_t aH[4][4];
#pragma unroll
            for (int mi = 0; mi < 4; mi++) {
                const uint32_t ad = sb
                    + (uint32_t)((c.a_row + mi * 16) * ROWB2 + (ko + c.a_kad) * 2);
                ldsm4(aH[mi], ad);
            }
            uint32_t bHf[4][4];
#pragma unroll
            for (int nf = 0; nf < 4; nf++) {
                const uint32_t bd = sb + ST_B
                    + (uint32_t)((c.b_row + nf * 16) * ROWB2 + (ko + c.b_kad) * 2);
                ldsm4(bHf[nf], bd);
            }
#pragma unroll
            for (int mi = 0; mi < 4; mi++) {
#pragma unroll
                for (int ni = 0; ni < 8; ni++) {
                    const uint32_t* bh = &bHf[ni >> 1][(ni & 1) * 2];
                    mma16816(acc[mi][ni], aH[mi], bh[0], bh[1]);
                }
            }
        }
    }
}

// ============================================================================
// Fused projections: one launch, grid (12, 128). All outputs fp16-hi only.
//   z = blockIdx.x>>2:  0 -> Q,  1 -> K',  2 -> V (transposed per batch)
// ============================================================================
__global__ __launch_bounds__(NTH, 2)
void proj3(const __half* __restrict__ xsh, const __half* __restrict__ xrh,
           const __half* __restrict__ wqh, const __half* __restrict__ wql,
           const __half* __restrict__ wkh, const __half* __restrict__ wkl,
           const __half* __restrict__ wvh, const __half* __restrict__ wvl,
           const float* __restrict__ bq, const float* __restrict__ bk,
           const float* __restrict__ bv, float sc,
           __half* __restrict__ qh, __half* __restrict__ kh,
           __half* __restrict__ vth)
{
    extern __shared__ char smem[];
    TileCtx c = make_ctx(smem_u32(smem));

    const int z  = blockIdx.x >> 2;
    const int n0 = (blockIdx.x & 3) * BN;
    const int m0 = blockIdx.y * BM;

    const __half* AH = (z == 1) ? xrh : xsh;
    const __half* BH = (z == 0) ? wqh : (z == 1) ? wkh : wvh;
    const __half* BL = (z == 0) ? wql : (z == 1) ? wkl : wvl;
    const float* bias = (z == 0) ? bq : (z == 1) ? bk : bv;
    const float alpha = (z == 0) ? sc : 1.0f;
    const float bcoef = (z == 0) ? sc : (z == 1) ? 2.0f : 1.0f;

    float acc[4][8][4];
    mainloop_proj(c, AH, BH, BL, m0, n0, HD, acc);

    const int rq = c.lane >> 2;
    const int cq = (c.lane & 3) * 2;

    if (z == 2) {
        // stage hi tile transposed in smem, then coalesced global writes
        __syncthreads();
        __half* bufh = (__half*)smem;
#pragma unroll
        for (int mi = 0; mi < 4; mi++) {
#pragma unroll
            for (int ni = 0; ni < 8; ni++) {
                const float* a4 = acc[mi][ni];
                const int lm = c.warpM * 64 + mi * 16 + rq;
                const int ln = c.warpN * 64 + ni * 8 + cq;
                const float b0 = bcoef * __ldg(&bias[n0 + ln]);
                const float b1 = bcoef * __ldg(&bias[n0 + ln + 1]);
#pragma unroll
                for (int h = 0; h < 2; h++) {
                    const int m = lm + h * 8;
                    bufh[ln * TSTR + m]       = __float2half(alpha * a4[2 * h]     + b0);
                    bufh[(ln + 1) * TSTR + m] = __float2half(alpha * a4[2 * h + 1] + b1);
                }
            }
        }
        __syncthreads();
        const int ncol = c.tid;                          // 0..127
        const __half* src = bufh + ncol * TSTR;
        const int bb  = m0 >> 12;
        const int m0s = m0 & 4095;
        __half* dst = vth + ((size_t)bb * HD + n0 + ncol) * SEQ + m0s;
#pragma unroll
        for (int q = 0; q < 16; q++)
            ((uint4*)dst)[q] = ((const uint4*)src)[q];
        return;
    }

    __half* O1 = (z == 0) ? qh : kh;
#pragma unroll
    for (int mi = 0; mi < 4; mi++) {
#pragma unroll
        for (int ni = 0; ni < 8; ni++) {
            const int mrow = m0 + c.warpM * 64 + mi * 16 + rq;
            const int ncol = n0 + c.warpN * 64 + ni * 8 + cq;
            const float* a4 = acc[mi][ni];
            const float b0 = bcoef * __ldg(&bias[ncol]);
            const float b1 = bcoef * __ldg(&bias[ncol + 1]);
#pragma unroll
            for (int h = 0; h < 2; h++) {
                const int m = mrow + h * 8;
                const __half h0 = __float2half(alpha * a4[2 * h]     + b0);
                const __half h1 = __float2half(alpha * a4[2 * h + 1] + b1);
                *(__half2*)(O1 + (size_t)m * HD + ncol) = __halves2half2(h0, h1);
            }
        }
    }
}

// ============================================================================
// QK + fused exp epilogue: ph = fp16(exp(Q·K'^T)/16), rowsum += row partials.
// grid (SEQ/BN, SEQ/BM, NB).
// ============================================================================
__global__ __launch_bounds__(NTH, 2)
void mma_qk(const __half* __restrict__ qg, const __half* __restrict__ kg,
            __half* __restrict__ ph, float* __restrict__ rowsum)
{
    extern __shared__ char smem[];
    TileCtx c = make_ctx(smem_u32(smem));

    const int m0 = blockIdx.y * BM;
    const int n0 = blockIdx.x * BN;
    const __half* AH = qg + (size_t)blockIdx.z * SEQ * HD;
    const __half* BH = kg + (size_t)blockIdx.z * SEQ * HD;

    float acc[4][8][4];
    mainloop_big(c, AH, BH, m0, n0, HD, acc);

    const int rq = c.lane >> 2;
    const int cq = (c.lane & 3) * 2;
    const size_t bO = (size_t)blockIdx.z * SEQ * SEQ;
    float* rs = rowsum + blockIdx.z * SEQ;

#pragma unroll
    for (int mi = 0; mi < 4; mi++) {
#pragma unroll
        for (int h = 0; h < 2; h++) {
            const int mrow = m0 + c.warpM * 64 + mi * 16 + rq + h * 8;
            float rsum = 0.0f;
            __half2 st[8];
#pragma unroll
            for (int ni = 0; ni < 8; ni++) {
                const float e0 = fexp(acc[mi][ni][2 * h]);
                const float e1 = fexp(acc[mi][ni][2 * h + 1]);
                rsum += e0 + e1;
                st[ni] = __halves2half2(__float2half(e0 * PSCALE),
                                        __float2half(e1 * PSCALE));
            }
#pragma unroll
            for (int ni = 0; ni < 8; ni++) {
                const int ncol = n0 + c.warpN * 64 + ni * 8 + cq;
                *(__half2*)(ph + bO + (size_t)mrow * SEQ + ncol) = st[ni];
            }
            // reduce over the 4 lanes sharing this row (lane bits 0-1)
            rsum += __shfl_xor_sync(0xffffffffu, rsum, 1);
            rsum += __shfl_xor_sync(0xffffffffu, rsum, 2);
            if ((c.lane & 3) == 0) atomicAdd(&rs[mrow], rsum);
        }
    }
}

// ============================================================================
// PV + deferred normalization: out = (P_scaled · Vt^T) * 16 / rowsum[row].
// grid (HD/BN, SEQ/BM, NB).
// ============================================================================
__global__ __launch_bounds__(NTH, 2)
void mma_pv(const __half* __restrict__ pg, const __half* __restrict__ vg,
            const float* __restrict__ rowsum, float* __restrict__ out)
{
    extern __shared__ char smem[];
    TileCtx c = make_ctx(smem_u32(smem));

    const int m0 = blockIdx.y * BM;
    const int n0 = blockIdx.x * BN;
    const __half* AH = pg + (size_t)blockIdx.z * SEQ * SEQ;
    const __half* BH = vg + (size_t)blockIdx.z * HD * SEQ;
    float* O = out + (size_t)blockIdx.z * SEQ * HD;
    const float* rs = rowsum + blockIdx.z * SEQ;

    float acc[4][8][4];
    mainloop_big(c, AH, BH, m0, n0, SEQ, acc);

    const int rq = c.lane >> 2;
    const int cq = (c.lane & 3) * 2;
#pragma unroll
    for (int mi = 0; mi < 4; mi++) {
        const int mrow = m0 + c.warpM * 64 + mi * 16 + rq;
        const float inv0 = 16.0f / __ldg(&rs[mrow]);
        const float inv1 = 16.0f / __ldg(&rs[mrow + 8]);
#pragma unroll
        for (int ni = 0; ni < 8; ni++) {
            const int ncol = n0 + c.warpN * 64 + ni * 8 + cq;
            const float* a4 = acc[mi][ni];
            *(float2*)(O + (size_t)mrow * HD + ncol) =
                make_float2(a4[0] * inv0, a4[1] * inv0);
            *(float2*)(O + (size_t)(mrow + 8) * HD + ncol) =
                make_float2(a4[2] * inv1, a4[3] * inv1);
        }
    }
}

// ============================================================================
// split / zero kernels
// ============================================================================
__global__ void split_x(const float* __restrict__ x, const float* __restrict__ rp,
                        __half* __restrict__ xsh, __half* __restrict__ xrh)
{
    const int z = blockIdx.z;
    const int i = (blockIdx.x * blockDim.x + threadIdx.x) * 4;
    float4 v = *(const float4*)(x + i);
    if (z) {
        const float4 u = *(const float4*)(rp + i);
        v.x += u.x; v.y += u.y; v.z += u.z; v.w += u.w;
    }
    __half* hi = z ? xrh : xsh;
    *(__half2*)(hi + i)     = __halves2half2(__float2half(v.x), __float2half(v.y));
    *(__half2*)(hi + i + 2) = __halves2half2(__float2half(v.z), __float2half(v.w));
}

__global__ void split_w(const float* __restrict__ w0, const float* __restrict__ w1,
                        const float* __restrict__ w2,
                        __half* __restrict__ h0p, __half* __restrict__ l0p,
                        __half* __restrict__ h1p, __half* __restrict__ l1p,
                        __half* __restrict__ h2p, __half* __restrict__ l2p)
{
    const int z = blockIdx.z;
    const float* a = (z == 0) ? w0 : (z == 1) ? w1 : w2;
    __half* hi = (z == 0) ? h0p : (z == 1) ? h1p : h2p;
    __half* lo = (z == 0) ? l0p : (z == 1) ? l1p : l2p;
    const int i = (blockIdx.x * blockDim.x + threadIdx.x) * 4;
    const float4 v = *(const float4*)(a + i);
    const __half h0 = __float2half(v.x), h1 = __float2half(v.y);
    const __half h2 = __float2half(v.z), h3 = __float2half(v.w);
    *(__half2*)(hi + i)     = __halves2half2(h0, h1);
    *(__half2*)(hi + i + 2) = __halves2half2(h2, h3);
    *(__half2*)(lo + i)     = __halves2half2(__float2half(v.x - __half2float(h0)),
                                             __float2half(v.y - __half2float(h1)));
    *(__half2*)(lo + i + 2) = __halves2half2(__float2half(v.z - __half2float(h2)),
                                             __float2half(v.w - __half2float(h3)));
}

__global__ void zero_rs(float* __restrict__ rs)
{
    const int i = (blockIdx.x * blockDim.x + threadIdx.x) * 4;
    *(float4*)(rs + i) = make_float4(0.f, 0.f, 0.f, 0.f);
}

// ============================================================================
// kernel_launch
// ============================================================================
extern "C" void kernel_launch(void* const* d_in, const int* in_sizes, int n_in,
                              void* d_out, int out_size)
{
    (void)in_sizes; (void)n_in; (void)out_size;
    const float* x  = (const float*)d_in[0];
    const float* rp = (const float*)d_in[1];
    const float* Wq = (const float*)d_in[2];
    const float* bq = (const float*)d_in[3];
    const float* Wk = (const float*)d_in[4];
    const float* bk = (const float*)d_in[5];
    const float* Wv = (const float*)d_in[6];
    const float* bv = (const float*)d_in[7];
    float* out = (float*)d_out;

    __half *xsh, *xrh, *wqh, *wql, *wkh, *wkl, *wvh, *wvl;
    __half *qh, *kh, *vth, *ph;
    float* rs;
    cudaGetSymbolAddress((void**)&xsh, g_xsh);
    cudaGetSymbolAddress((void**)&xrh, g_xrh);
    cudaGetSymbolAddress((void**)&wqh, g_wqh); cudaGetSymbolAddress((void**)&wql, g_wql);
    cudaGetSymbolAddress((void**)&wkh, g_wkh); cudaGetSymbolAddress((void**)&wkl, g_wkl);
    cudaGetSymbolAddress((void**)&wvh, g_wvh); cudaGetSymbolAddress((void**)&wvl, g_wvl);
    cudaGetSymbolAddress((void**)&qh,  g_qh);
    cudaGetSymbolAddress((void**)&kh,  g_kh);
    cudaGetSymbolAddress((void**)&vth, g_vth);
    cudaGetSymbolAddress((void**)&ph,  g_ph);
    cudaGetSymbolAddress((void**)&rs,  g_rs);

    cudaFuncSetAttribute((const void*)proj3,
                         cudaFuncAttributeMaxDynamicSharedMemorySize, SMEM_PROJ);
    cudaFuncSetAttribute((const void*)mma_qk,
                         cudaFuncAttributeMaxDynamicSharedMemorySize, SMEM_BIG);
    cudaFuncSetAttribute((const void*)mma_pv,
                         cudaFuncAttributeMaxDynamicSharedMemorySize, SMEM_BIG);

    const float sc = (float)(1.0 / sqrt((double)HD));

    // --- zero row sums + splits ---
    zero_rs<<<NB * SEQ / 1024, 256>>>(rs);
    split_x<<<dim3(TOK * HD / 1024, 1, 2), 256>>>(x, rp, xsh, xrh);
    split_w<<<dim3(HD * HD / 1024, 1, 3), 256>>>(Wq, Wk, Wv,
                                                 wqh, wql, wkh, wkl, wvh, wvl);

    // --- fused projections: Q | K' | V(transposed), one launch, hi outputs ---
    proj3<<<dim3(12, TOK / BM), NTH, SMEM_PROJ>>>(
        xsh, xrh, wqh, wql, wkh, wkl, wvh, wvl,
        bq, bk, bv, sc, qh, kh, vth);

    // --- QK with fused exp + row-sum epilogue (BK=64 mainloop) ---
    mma_qk<<<dim3(SEQ / BN, SEQ / BM, NB), NTH, SMEM_BIG>>>(qh, kh, ph, rs);

    // --- PV with deferred normalization (BK=64 mainloop) ---
    mma_pv<<<dim3(HD / BN, SEQ / BM, NB), NTH, SMEM_BIG>>>(ph, vth, rs, out);
}

// round 16
// speedup vs baseline: 1.1639x; 1.1639x over previous
#include <cuda_runtime.h>
#include <cuda_fp16.h>
#include <math.h>
#include <stdint.h>

// ============================================================================
// ResponseAttention via mma.sync (m16n8k16 fp16), pure fp16 GEMMs + fp32 acc.
//   scores = Qs · K'^T, Qs=(x·Wq^T+bq)/sqrt(H), K'=(x+rp)·Wk^T+2bk
//   out    = softmax(scores) · V   (V stored transposed so P·V is NT too)
// All operands truncated to fp16-hi; every GEMM is 1-MMA (fp32 accumulate).
// Softmax fused into QK epilogue (exp on FMA pipe, no max pass) + deferred
// row normalization in PV epilogue.
// R16: reverted R15's BK=64 (ROWB2=144 had 2-way ldsm bank conflicts —
// 72 words mod 32 = 8 — plus 221KB smem stripped L1; both regressions).
// Dropped W_lo from projections: outputs are fp16-truncated anyway, so the
// W-split only protected bits the truncation discards coherently-ish; adds
// ~2.8e-4/proj in quadrature -> predicted ~6.5e-4 < 1e-3 gate.
// tcgen05 unavailable (compute_103 virtual arch) — mma.sync is the path.
// B=4, S=4096, H=512.
// ============================================================================

#define BM 128
#define BN 128
#define BK 32
#define NSTAGE 3
#define NTH 128

#define TOK 16384
#define HD  512
#define SEQ 4096
#define NB  4

// smem: rows of 32 fp16 padded to 40 halves (80 B) -> conflict-free ldsm
#define ROWB 80
#define MATB (128 * ROWB)                       // 128x32 fp16 matrix: 10240 B
#define SMEM_GEMM (NSTAGE * 2 * MATB)           // 61440: A B

#define TSTR 136                                // transpose-buffer row stride (halves)
#define PSCALE 0.0625f                          // P stored as e/16 (overflow headroom)

// ---------------------------- scratch ------------------------------------
__device__ __half g_xsh[TOK * HD];
__device__ __half g_xrh[TOK * HD];
__device__ __half g_wqh[HD * HD];
__device__ __half g_wkh[HD * HD];
__device__ __half g_wvh[HD * HD];
__device__ __half g_qh[TOK * HD];
__device__ __half g_kh[TOK * HD];
__device__ __half g_vth[TOK * HD];
__device__ __half g_ph[(size_t)NB * SEQ * SEQ];
__device__ float  g_rs[NB * SEQ];               // softmax row sums (unscaled)

// ---------------------------- helpers ------------------------------------
__device__ __forceinline__ uint32_t smem_u32(const void* p) {
    uint32_t a;
    asm("{ .reg .u64 t; cvta.to.shared.u64 t, %1; cvt.u32.u64 %0, t; }"
        : "=r"(a) : "l"(p));
    return a;
}
__device__ __forceinline__ void cp16(uint32_t s, const void* g) {
    asm volatile("cp.async.cg.shared.global [%0], [%1], 16;" :: "r"(s), "l"(g));
}
#define CP_COMMIT() asm volatile("cp.async.commit_group;")
#define CP_WAIT(n)  asm volatile("cp.async.wait_group %0;" :: "n"(n))

__device__ __forceinline__ void ldsm4(uint32_t r[4], uint32_t addr) {
    asm volatile("ldmatrix.sync.aligned.m8n8.x4.shared.b16 {%0,%1,%2,%3}, [%4];"
        : "=r"(r[0]), "=r"(r[1]), "=r"(r[2]), "=r"(r[3]) : "r"(addr));
}
__device__ __forceinline__ void mma16816(float acc[4], const uint32_t a[4],
                                         const uint32_t b0, const uint32_t b1) {
    asm volatile(
        "mma.sync.aligned.m16n8k16.row.col.f32.f16.f16.f32 "
        "{%0,%1,%2,%3}, {%4,%5,%6,%7}, {%8,%9}, {%0,%1,%2,%3};"
        : "+f"(acc[0]), "+f"(acc[1]), "+f"(acc[2]), "+f"(acc[3])
        : "r"(a[0]), "r"(a[1]), "r"(a[2]), "r"(a[3]), "r"(b0), "r"(b1));
}

// fast exp on FMA/ALU pipes (exp2 magic-round + deg-5 poly, rel err ~2e-6)
__device__ __forceinline__ float fexp(float x) {
    x = fmaxf(x, -87.0f);
    const float t = x * 1.4426950408889634f;
    const float z = t + 12582912.0f;            // 1.5 * 2^23: round to nearest
    const int   n = __float_as_int(z);
    const float f = t - (z - 12582912.0f);
    float p = 1.3333558146e-3f;
    p = fmaf(p, f, 9.6181291076e-3f);
    p = fmaf(p, f, 5.5504108664e-2f);
    p = fmaf(p, f, 2.4022650696e-1f);
    p = fmaf(p, f, 6.9314718056e-1f);
    p = fmaf(p, f, 1.0f);
    return __int_as_float(__float_as_int(p) + (n << 23));
}

// ---------------------------------------------------------------------------
// TileCtx: 4 warps, warp grid 2M x 2N, warp tile 64x64. acc[4][8][4].
// ---------------------------------------------------------------------------
struct TileCtx {
    uint32_t sbase;
    int tid, lane, wid, warpM, warpN;
    int a_row, a_kad, b_row, b_kad;
};

__device__ __forceinline__ TileCtx make_ctx(uint32_t sbase) {
    TileCtx c;
    c.sbase = sbase;
    c.tid  = threadIdx.x;
    c.lane = c.tid & 31;
    c.wid  = c.tid >> 5;
    c.warpM = c.wid & 1;
    c.warpN = c.wid >> 1;             // 0..1
    c.a_row = c.warpM * 64 + (c.lane & 15);
    c.a_kad = (c.lane >> 4) << 3;
    c.b_row = c.warpN * 64 + (c.lane & 7) + ((c.lane >> 4) << 3);
    c.b_kad = ((c.lane >> 3) & 1) << 3;
    return c;
}

// ---------------------------------------------------------------------------
// Unified 1-MMA mainloop: C[128,128] tile of A[M,K] * B[N,K]^T, fp32 accum.
// BK=32, 3-stage cp.async pipeline, 2-matrix stage.
// ---------------------------------------------------------------------------
__device__ __forceinline__ void mainloop(
    const TileCtx& c, const __half* AH, const __half* BH,
    int m0, int n0, int K, float acc[4][8][4])
{
    constexpr uint32_t ST_B = MATB;
    constexpr uint32_t STG  = 2 * MATB;

#pragma unroll
    for (int mi = 0; mi < 4; mi++)
#pragma unroll
        for (int ni = 0; ni < 8; ni++)
#pragma unroll
            for (int r = 0; r < 4; r++) acc[mi][ni][r] = 0.0f;

    auto fill = [&](int stg, int kt) {
        const int kc = kt * BK;
        const uint32_t sb = c.sbase + stg * STG;
#pragma unroll
        for (int j = 0; j < 4; j++) {
            const int idx = c.tid + NTH * j;
            const int r  = idx >> 2;
            const int ch = idx & 3;
            const uint32_t so = (uint32_t)(r * ROWB + ch * 16);
            cp16(sb + so,        AH + (size_t)(m0 + r) * K + kc + ch * 8);
            cp16(sb + ST_B + so, BH + (size_t)(n0 + r) * K + kc + ch * 8);
        }
        CP_COMMIT();
    };

    const int KT = K / BK;
    fill(0, 0);
    fill(1, 1);

    for (int kt = 0; kt < KT; kt++) {
        if (kt == KT - 1) { CP_WAIT(0); } else { CP_WAIT(1); }
        __syncthreads();
        const uint32_t sb = c.sbase + (kt % NSTAGE) * STG;
        if (kt + NSTAGE - 1 < KT) fill((kt + NSTAGE - 1) % NSTAGE, kt + NSTAGE - 1);

#pragma unroll
        for (int ks = 0; ks < 2; ks++) {
            const int ko = ks * 16;
            uint32_t aH[4][4];
#pragma unroll
            for (int mi = 0; mi < 4; mi++) {
                const uint32_t ad = sb
                    + (uint32_t)((c.a_row + mi * 16) * ROWB + (ko + c.a_kad) * 2);
                ldsm4(aH[mi], ad);
            }
            uint32_t bHf[4][4];
#pragma unroll
            for (int nf = 0; nf < 4; nf++) {
                const uint32_t bd = sb + ST_B
                    + (uint32_t)((c.b_row + nf * 16) * ROWB + (ko + c.b_kad) * 2);
                ldsm4(bHf[nf], bd);
            }
#pragma unroll
            for (int mi = 0; mi < 4; mi++) {
#pragma unroll
                for (int ni = 0; ni < 8; ni++) {
                    const uint32_t* bh = &bHf[ni >> 1][(ni & 1) * 2];
                    mma16816(acc[mi][ni], aH[mi], bh[0], bh[1]);
                }
            }
        }
    }
}

// ============================================================================
// Fused projections: one launch, grid (12, 128). All outputs fp16-hi only.
//   z = blockIdx.x>>2:  0 -> Q,  1 -> K',  2 -> V (transposed per batch)
// ============================================================================
__global__ __launch_bounds__(NTH, 2)
void proj3(const __half* __restrict__ xsh, const __half* __restrict__ xrh,
           const __half* __restrict__ wqh, const __half* __restrict__ wkh,
           const __half* __restrict__ wvh,
           const float* __restrict__ bq, const float* __restrict__ bk,
           const float* __restrict__ bv, float sc,
           __half* __restrict__ qh, __half* __restrict__ kh,
           __half* __restrict__ vth)
{
    extern __shared__ char smem[];
    TileCtx c = make_ctx(smem_u32(smem));

    const int z  = blockIdx.x >> 2;
    const int n0 = (blockIdx.x & 3) * BN;
    const int m0 = blockIdx.y * BM;

    const __half* AH = (z == 1) ? xrh : xsh;
    const __half* BH = (z == 0) ? wqh : (z == 1) ? wkh : wvh;
    const float* bias = (z == 0) ? bq : (z == 1) ? bk : bv;
    const float alpha = (z == 0) ? sc : 1.0f;
    const float bcoef = (z == 0) ? sc : (z == 1) ? 2.0f : 1.0f;

    float acc[4][8][4];
    mainloop(c, AH, BH, m0, n0, HD, acc);

    const int rq = c.lane >> 2;
    const int cq = (c.lane & 3) * 2;

    if (z == 2) {
        // stage hi tile transposed in smem, then coalesced global writes
        __syncthreads();
        __half* bufh = (__half*)smem;
#pragma unroll
        for (int mi = 0; mi < 4; mi++) {
#pragma unroll
            for (int ni = 0; ni < 8; ni++) {
                const float* a4 = acc[mi][ni];
                const int lm = c.warpM * 64 + mi * 16 + rq;
                const int ln = c.warpN * 64 + ni * 8 + cq;
                const float b0 = bcoef * __ldg(&bias[n0 + ln]);
                const float b1 = bcoef * __ldg(&bias[n0 + ln + 1]);
#pragma unroll
                for (int h = 0; h < 2; h++) {
                    const int m = lm + h * 8;
                    bufh[ln * TSTR + m]       = __float2half(alpha * a4[2 * h]     + b0);
                    bufh[(ln + 1) * TSTR + m] = __float2half(alpha * a4[2 * h + 1] + b1);
                }
            }
        }
        __syncthreads();
        const int ncol = c.tid;                          // 0..127
        const __half* src = bufh + ncol * TSTR;
        const int bb  = m0 >> 12;
        const int m0s = m0 & 4095;
        __half* dst = vth + ((size_t)bb * HD + n0 + ncol) * SEQ + m0s;
#pragma unroll
        for (int q = 0; q < 16; q++)
            ((uint4*)dst)[q] = ((const uint4*)src)[q];
        return;
    }

    __half* O1 = (z == 0) ? qh : kh;
#pragma unroll
    for (int mi = 0; mi < 4; mi++) {
#pragma unroll
        for (int ni = 0; ni < 8; ni++) {
            const int mrow = m0 + c.warpM * 64 + mi * 16 + rq;
            const int ncol = n0 + c.warpN * 64 + ni * 8 + cq;
            const float* a4 = acc[mi][ni];
            const float b0 = bcoef * __ldg(&bias[ncol]);
            const float b1 = bcoef * __ldg(&bias[ncol + 1]);
#pragma unroll
            for (int h = 0; h < 2; h++) {
                const int m = mrow + h * 8;
                const __half h0 = __float2half(alpha * a4[2 * h]     + b0);
                const __half h1 = __float2half(alpha * a4[2 * h + 1] + b1);
                *(__half2*)(O1 + (size_t)m * HD + ncol) = __halves2half2(h0, h1);
            }
        }
    }
}

// ============================================================================
// QK + fused exp epilogue: ph = fp16(exp(Q·K'^T)/16), rowsum += row partials.
// grid (SEQ/BN, SEQ/BM, NB).
// ============================================================================
__global__ __launch_bounds__(NTH, 2)
void mma_qk(const __half* __restrict__ qg, const __half* __restrict__ kg,
            __half* __restrict__ ph, float* __restrict__ rowsum)
{
    extern __shared__ char smem[];
    TileCtx c = make_ctx(smem_u32(smem));

    const int m0 = blockIdx.y * BM;
    const int n0 = blockIdx.x * BN;
    const __half* AH = qg + (size_t)blockIdx.z * SEQ * HD;
    const __half* BH = kg + (size_t)blockIdx.z * SEQ * HD;

    float acc[4][8][4];
    mainloop(c, AH, BH, m0, n0, HD, acc);

    const int rq = c.lane >> 2;
    const int cq = (c.lane & 3) * 2;
    const size_t bO = (size_t)blockIdx.z * SEQ * SEQ;
    float* rs = rowsum + blockIdx.z * SEQ;

#pragma unroll
    for (int mi = 0; mi < 4; mi++) {
#pragma unroll
        for (int h = 0; h < 2; h++) {
            const int mrow = m0 + c.warpM * 64 + mi * 16 + rq + h * 8;
            float rsum = 0.0f;
            __half2 st[8];
#pragma unroll
            for (int ni = 0; ni < 8; ni++) {
                const float e0 = fexp(acc[mi][ni][2 * h]);
                const float e1 = fexp(acc[mi][ni][2 * h + 1]);
                rsum += e0 + e1;
                st[ni] = __halves2half2(__float2half(e0 * PSCALE),
                                        __float2half(e1 * PSCALE));
            }
#pragma unroll
            for (int ni = 0; ni < 8; ni++) {
                const int ncol = n0 + c.warpN * 64 + ni * 8 + cq;
                *(__half2*)(ph + bO + (size_t)mrow * SEQ + ncol) = st[ni];
            }
            // reduce over the 4 lanes sharing this row (lane bits 0-1)
            rsum += __shfl_xor_sync(0xffffffffu, rsum, 1);
            rsum += __shfl_xor_sync(0xffffffffu, rsum, 2);
            if ((c.lane & 3) == 0) atomicAdd(&rs[mrow], rsum);
        }
    }
}

// ============================================================================
// PV + deferred normalization: out = (P_scaled · Vt^T) * 16 / rowsum[row].
// grid (HD/BN, SEQ/BM, NB).
// ============================================================================
__global__ __launch_bounds__(NTH, 2)
void mma_pv(const __half* __restrict__ pg, const __half* __restrict__ vg,
            const float* __restrict__ rowsum, float* __restrict__ out)
{
    extern __shared__ char smem[];
    TileCtx c = make_ctx(smem_u32(smem));

    const int m0 = blockIdx.y * BM;
    const int n0 = blockIdx.x * BN;
    const __half* AH = pg + (size_t)blockIdx.z * SEQ * SEQ;
    const __half* BH = vg + (size_t)blockIdx.z * HD * SEQ;
    float* O = out + (size_t)blockIdx.z * SEQ * HD;
    const float* rs = rowsum + blockIdx.z * SEQ;

    float acc[4][8][4];
    mainloop(c, AH, BH, m0, n0, SEQ, acc);

    const int rq = c.lane >> 2;
    const int cq = (c.lane & 3) * 2;
#pragma unroll
    for (int mi = 0; mi < 4; mi++) {
        const int mrow = m0 + c.warpM * 64 + mi * 16 + rq;
        const float inv0 = 16.0f / __ldg(&rs[mrow]);
        const float inv1 = 16.0f / __ldg(&rs[mrow + 8]);
#pragma unroll
        for (int ni = 0; ni < 8; ni++) {
            const int ncol = n0 + c.warpN * 64 + ni * 8 + cq;
            const float* a4 = acc[mi][ni];
            *(float2*)(O + (size_t)mrow * HD + ncol) =
                make_float2(a4[0] * inv0, a4[1] * inv0);
            *(float2*)(O + (size_t)(mrow + 8) * HD + ncol) =
                make_float2(a4[2] * inv1, a4[3] * inv1);
        }
    }
}

// ============================================================================
// split / zero kernels (fp16-hi only everywhere)
// ============================================================================
__global__ void split_x(const float* __restrict__ x, const float* __restrict__ rp,
                        __half* __restrict__ xsh, __half* __restrict__ xrh)
{
    const int z = blockIdx.z;
    const int i = (blockIdx.x * blockDim.x + threadIdx.x) * 4;
    float4 v = *(const float4*)(x + i);
    if (z) {
        const float4 u = *(const float4*)(rp + i);
        v.x += u.x; v.y += u.y; v.z += u.z; v.w += u.w;
    }
    __half* hi = z ? xrh : xsh;
    *(__half2*)(hi + i)     = __halves2half2(__float2half(v.x), __float2half(v.y));
    *(__half2*)(hi + i + 2) = __halves2half2(__float2half(v.z), __float2half(v.w));
}

__global__ void split_w(const float* __restrict__ w0, const float* __restrict__ w1,
                        const float* __restrict__ w2,
                        __half* __restrict__ h0p, __half* __restrict__ h1p,
                        __half* __restrict__ h2p)
{
    const int z = blockIdx.z;
    const float* a = (z == 0) ? w0 : (z == 1) ? w1 : w2;
    __half* hi = (z == 0) ? h0p : (z == 1) ? h1p : h2p;
    const int i = (blockIdx.x * blockDim.x + threadIdx.x) * 4;
    const float4 v = *(const float4*)(a + i);
    *(__half2*)(hi + i)     = __halves2half2(__float2half(v.x), __float2half(v.y));
    *(__half2*)(hi + i + 2) = __halves2half2(__float2half(v.z), __float2half(v.w));
}

__global__ void zero_rs(float* __restrict__ rs)
{
    const int i = (blockIdx.x * blockDim.x + threadIdx.x) * 4;
    *(float4*)(rs + i) = make_float4(0.f, 0.f, 0.f, 0.f);
}

// ============================================================================
// kernel_launch
// ============================================================================
extern "C" void kernel_launch(void* const* d_in, const int* in_sizes, int n_in,
                              void* d_out, int out_size)
{
    (void)in_sizes; (void)n_in; (void)out_size;
    const float* x  = (const float*)d_in[0];
    const float* rp = (const float*)d_in[1];
    const float* Wq = (const float*)d_in[2];
    const float* bq = (const float*)d_in[3];
    const float* Wk = (const float*)d_in[4];
    const float* bk = (const float*)d_in[5];
    const float* Wv = (const float*)d_in[6];
    const float* bv = (const float*)d_in[7];
    float* out = (float*)d_out;

    __half *xsh, *xrh, *wqh, *wkh, *wvh;
    __half *qh, *kh, *vth, *ph;
    float* rs;
    cudaGetSymbolAddress((void**)&xsh, g_xsh);
    cudaGetSymbolAddress((void**)&xrh, g_xrh);
    cudaGetSymbolAddress((void**)&wqh, g_wqh);
    cudaGetSymbolAddress((void**)&wkh, g_wkh);
    cudaGetSymbolAddress((void**)&wvh, g_wvh);
    cudaGetSymbolAddress((void**)&qh,  g_qh);
    cudaGetSymbolAddress((void**)&kh,  g_kh);
    cudaGetSymbolAddress((void**)&vth, g_vth);
    cudaGetSymbolAddress((void**)&ph,  g_ph);
    cudaGetSymbolAddress((void**)&rs,  g_rs);

    cudaFuncSetAttribute((const void*)proj3,
                         cudaFuncAttributeMaxDynamicSharedMemorySize, SMEM_GEMM);
    cudaFuncSetAttribute((const void*)mma_qk,
                         cudaFuncAttributeMaxDynamicSharedMemorySize, SMEM_GEMM);
    cudaFuncSetAttribute((const void*)mma_pv,
                         cudaFuncAttributeMaxDynamicSharedMemorySize, SMEM_GEMM);

    const float sc = (float)(1.0 / sqrt((double)HD));

    // --- zero row sums + splits (hi only) ---
    zero_rs<<<NB * SEQ / 1024, 256>>>(rs);
    split_x<<<dim3(TOK * HD / 1024, 1, 2), 256>>>(x, rp, xsh, xrh);
    split_w<<<dim3(HD * HD / 1024, 1, 3), 256>>>(Wq, Wk, Wv, wqh, wkh, wvh);

    // --- fused projections: Q | K' | V(transposed), one launch, 1-MMA ---
    proj3<<<dim3(12, TOK / BM), NTH, SMEM_GEMM>>>(
        xsh, xrh, wqh, wkh, wvh, bq, bk, bv, sc, qh, kh, vth);

    // --- QK with fused exp + row-sum epilogue ---
    mma_qk<<<dim3(SEQ / BN, SEQ / BM, NB), NTH, SMEM_GEMM>>>(qh, kh, ph, rs);

    // --- PV with deferred normalization ---
    mma_pv<<<dim3(HD / BN, SEQ / BM, NB), NTH, SMEM_GEMM>>>(ph, vth, rs, out);
}

// round 17
// speedup vs baseline: 1.2152x; 1.0440x over previous
#include <cuda_runtime.h>
#include <cuda_fp16.h>
#include <math.h>
#include <stdint.h>

// ============================================================================
// ResponseAttention via mma.sync (m16n8k16 fp16), pure fp16 GEMMs + fp32 acc.
//   scores = Qs · K'^T, Qs=(x·Wq^T+bq)/sqrt(H), K'=(x+rp)·Wk^T+2bk
//   out    = softmax(scores) · V   (V stored transposed so P·V is NT too)
// All operands truncated to fp16; every GEMM is 1 MMA/fragment, fp32 accum.
// Softmax fused into QK epilogue (FMA-pipe exp, no max pass) + deferred row
// normalization in PV epilogue. rel_err ~6.7e-4 (precision floor; no more
// precision-for-speed trades).
// R17 (conservative): prep fused — x is read ONCE for both xsh and xrh
// (was read twice across z-slices; -64MB DRAM) with zero_rs folded in;
// mainloop fill() hoisted after the ks=0 fragment loads so cp.async issue
// overlaps the MMA stretch instead of delaying the first LDSM.
// tcgen05 unavailable (compute_103 virtual arch) — mma.sync is the path.
// B=4, S=4096, H=512.
// ============================================================================

#define BM 128
#define BN 128
#define BK 32
#define NSTAGE 3
#define NTH 128

#define TOK 16384
#define HD  512
#define SEQ 4096
#define NB  4

// smem: rows of 32 fp16 padded to 40 halves (80 B) -> conflict-free ldsm
#define ROWB 80
#define MATB (128 * ROWB)                       // 128x32 fp16 matrix: 10240 B
#define SMEM_GEMM (NSTAGE * 2 * MATB)           // 61440: A B

#define TSTR 136                                // transpose-buffer row stride (halves)
#define PSCALE 0.0625f                          // P stored as e/16 (overflow headroom)

// ---------------------------- scratch ------------------------------------
__device__ __half g_xsh[TOK * HD];
__device__ __half g_xrh[TOK * HD];
__device__ __half g_wqh[HD * HD];
__device__ __half g_wkh[HD * HD];
__device__ __half g_wvh[HD * HD];
__device__ __half g_qh[TOK * HD];
__device__ __half g_kh[TOK * HD];
__device__ __half g_vth[TOK * HD];
__device__ __half g_ph[(size_t)NB * SEQ * SEQ];
__device__ float  g_rs[NB * SEQ];               // softmax row sums (unscaled)

// ---------------------------- helpers ------------------------------------
__device__ __forceinline__ uint32_t smem_u32(const void* p) {
    uint32_t a;
    asm("{ .reg .u64 t; cvta.to.shared.u64 t, %1; cvt.u32.u64 %0, t; }"
        : "=r"(a) : "l"(p));
    return a;
}
__device__ __forceinline__ void cp16(uint32_t s, const void* g) {
    asm volatile("cp.async.cg.shared.global [%0], [%1], 16;" :: "r"(s), "l"(g));
}
#define CP_COMMIT() asm volatile("cp.async.commit_group;")
#define CP_WAIT(n)  asm volatile("cp.async.wait_group %0;" :: "n"(n))

__device__ __forceinline__ void ldsm4(uint32_t r[4], uint32_t addr) {
    asm volatile("ldmatrix.sync.aligned.m8n8.x4.shared.b16 {%0,%1,%2,%3}, [%4];"
        : "=r"(r[0]), "=r"(r[1]), "=r"(r[2]), "=r"(r[3]) : "r"(addr));
}
__device__ __forceinline__ void mma16816(float acc[4], const uint32_t a[4],
                                         const uint32_t b0, const uint32_t b1) {
    asm volatile(
        "mma.sync.aligned.m16n8k16.row.col.f32.f16.f16.f32 "
        "{%0,%1,%2,%3}, {%4,%5,%6,%7}, {%8,%9}, {%0,%1,%2,%3};"
        : "+f"(acc[0]), "+f"(acc[1]), "+f"(acc[2]), "+f"(acc[3])
        : "r"(a[0]), "r"(a[1]), "r"(a[2]), "r"(a[3]), "r"(b0), "r"(b1));
}

// fast exp on FMA/ALU pipes (exp2 magic-round + deg-5 poly, rel err ~2e-6)
__device__ __forceinline__ float fexp(float x) {
    x = fmaxf(x, -87.0f);
    const float t = x * 1.4426950408889634f;
    const float z = t + 12582912.0f;            // 1.5 * 2^23: round to nearest
    const int   n = __float_as_int(z);
    const float f = t - (z - 12582912.0f);
    float p = 1.3333558146e-3f;
    p = fmaf(p, f, 9.6181291076e-3f);
    p = fmaf(p, f, 5.5504108664e-2f);
    p = fmaf(p, f, 2.4022650696e-1f);
    p = fmaf(p, f, 6.9314718056e-1f);
    p = fmaf(p, f, 1.0f);
    return __int_as_float(__float_as_int(p) + (n << 23));
}

// ---------------------------------------------------------------------------
// TileCtx: 4 warps, warp grid 2M x 2N, warp tile 64x64. acc[4][8][4].
// ---------------------------------------------------------------------------
struct TileCtx {
    uint32_t sbase;
    int tid, lane, wid, warpM, warpN;
    int a_row, a_kad, b_row, b_kad;
};

__device__ __forceinline__ TileCtx make_ctx(uint32_t sbase) {
    TileCtx c;
    c.sbase = sbase;
    c.tid  = threadIdx.x;
    c.lane = c.tid & 31;
    c.wid  = c.tid >> 5;
    c.warpM = c.wid & 1;
    c.warpN = c.wid >> 1;             // 0..1
    c.a_row = c.warpM * 64 + (c.lane & 15);
    c.a_kad = (c.lane >> 4) << 3;
    c.b_row = c.warpN * 64 + (c.lane & 7) + ((c.lane >> 4) << 3);
    c.b_kad = ((c.lane >> 3) & 1) << 3;
    return c;
}

// ---------------------------------------------------------------------------
// Unified 1-MMA mainloop: C[128,128] tile of A[M,K] * B[N,K]^T, fp32 accum.
// BK=32, 3-stage cp.async pipeline, 2-matrix stage. fill() issues AFTER the
// ks=0 fragment loads so LSU work overlaps the MMA stretch.
// ---------------------------------------------------------------------------
__device__ __forceinline__ void mainloop(
    const TileCtx& c, const __half* AH, const __half* BH,
    int m0, int n0, int K, float acc[4][8][4])
{
    constexpr uint32_t ST_B = MATB;
    constexpr uint32_t STG  = 2 * MATB;

#pragma unroll
    for (int mi = 0; mi < 4; mi++)
#pragma unroll
        for (int ni = 0; ni < 8; ni++)
#pragma unroll
            for (int r = 0; r < 4; r++) acc[mi][ni][r] = 0.0f;

    auto fill = [&](int stg, int kt) {
        const int kc = kt * BK;
        const uint32_t sb = c.sbase + stg * STG;
#pragma unroll
        for (int j = 0; j < 4; j++) {
            const int idx = c.tid + NTH * j;
            const int r  = idx >> 2;
            const int ch = idx & 3;
            const uint32_t so = (uint32_t)(r * ROWB + ch * 16);
            cp16(sb + so,        AH + (size_t)(m0 + r) * K + kc + ch * 8);
            cp16(sb + ST_B + so, BH + (size_t)(n0 + r) * K + kc + ch * 8);
        }
        CP_COMMIT();
    };

    const int KT = K / BK;
    fill(0, 0);
    fill(1, 1);

    for (int kt = 0; kt < KT; kt++) {
        if (kt == KT - 1) { CP_WAIT(0); } else { CP_WAIT(1); }
        __syncthreads();
        const uint32_t sb = c.sbase + (kt % NSTAGE) * STG;

#pragma unroll
        for (int ks = 0; ks < 2; ks++) {
            const int ko = ks * 16;
            uint32_t aH[4][4];
#pragma unroll
            for (int mi = 0; mi < 4; mi++) {
                const uint32_t ad = sb
                    + (uint32_t)((c.a_row + mi * 16) * ROWB + (ko + c.a_kad) * 2);
                ldsm4(aH[mi], ad);
            }
            uint32_t bHf[4][4];
#pragma unroll
            for (int nf = 0; nf < 4; nf++) {
                const uint32_t bd = sb + ST_B
                    + (uint32_t)((c.b_row + nf * 16) * ROWB + (ko + c.b_kad) * 2);
                ldsm4(bHf[nf], bd);
            }
            // issue next-stage cp.async AFTER ks=0 fragment loads: the LSU
            // traffic overlaps the MMA stretch instead of delaying it.
            if (ks == 0 && kt + NSTAGE - 1 < KT)
                fill((kt + NSTAGE - 1) % NSTAGE, kt + NSTAGE - 1);
#pragma unroll
            for (int mi = 0; mi < 4; mi++) {
#pragma unroll
                for (int ni = 0; ni < 8; ni++) {
                    const uint32_t* bh = &bHf[ni >> 1][(ni & 1) * 2];
                    mma16816(acc[mi][ni], aH[mi], bh[0], bh[1]);
                }
            }
        }
    }
}

// ============================================================================
// Fused projections: one launch, grid (12, 128). All outputs fp16-hi only.
//   z = blockIdx.x>>2:  0 -> Q,  1 -> K',  2 -> V (transposed per batch)
// ============================================================================
__global__ __launch_bounds__(NTH, 2)
void proj3(const __half* __restrict__ xsh, const __half* __restrict__ xrh,
           const __half* __restrict__ wqh, const __half* __restrict__ wkh,
           const __half* __restrict__ wvh,
           const float* __restrict__ bq, const float* __restrict__ bk,
           const float* __restrict__ bv, float sc,
           __half* __restrict__ qh, __half* __restrict__ kh,
           __half* __restrict__ vth)
{
    extern __shared__ char smem[];
    TileCtx c = make_ctx(smem_u32(smem));

    const int z  = blockIdx.x >> 2;
    const int n0 = (blockIdx.x & 3) * BN;
    const int m0 = blockIdx.y * BM;

    const __half* AH = (z == 1) ? xrh : xsh;
    const __half* BH = (z == 0) ? wqh : (z == 1) ? wkh : wvh;
    const float* bias = (z == 0) ? bq : (z == 1) ? bk : bv;
    const float alpha = (z == 0) ? sc : 1.0f;
    const float bcoef = (z == 0) ? sc : (z == 1) ? 2.0f : 1.0f;

    float acc[4][8][4];
    mainloop(c, AH, BH, m0, n0, HD, acc);

    const int rq = c.lane >> 2;
    const int cq = (c.lane & 3) * 2;

    if (z == 2) {
        // stage hi tile transposed in smem, then coalesced global writes
        __syncthreads();
        __half* bufh = (__half*)smem;
#pragma unroll
        for (int mi = 0; mi < 4; mi++) {
#pragma unroll
            for (int ni = 0; ni < 8; ni++) {
                const float* a4 = acc[mi][ni];
                const int lm = c.warpM * 64 + mi * 16 + rq;
                const int ln = c.warpN * 64 + ni * 8 + cq;
                const float b0 = bcoef * __ldg(&bias[n0 + ln]);
                const float b1 = bcoef * __ldg(&bias[n0 + ln + 1]);
#pragma unroll
                for (int h = 0; h < 2; h++) {
                    const int m = lm + h * 8;
                    bufh[ln * TSTR + m]       = __float2half(alpha * a4[2 * h]     + b0);
                    bufh[(ln + 1) * TSTR + m] = __float2half(alpha * a4[2 * h + 1] + b1);
                }
            }
        }
        __syncthreads();
        const int ncol = c.tid;                          // 0..127
        const __half* src = bufh + ncol * TSTR;
        const int bb  = m0 >> 12;
        const int m0s = m0 & 4095;
        __half* dst = vth + ((size_t)bb * HD + n0 + ncol) * SEQ + m0s;
#pragma unroll
        for (int q = 0; q < 16; q++)
            ((uint4*)dst)[q] = ((const uint4*)src)[q];
        return;
    }

    __half* O1 = (z == 0) ? qh : kh;
#pragma unroll
    for (int mi = 0; mi < 4; mi++) {
#pragma unroll
        for (int ni = 0; ni < 8; ni++) {
            const int mrow = m0 + c.warpM * 64 + mi * 16 + rq;
            const int ncol = n0 + c.warpN * 64 + ni * 8 + cq;
            const float* a4 = acc[mi][ni];
            const float b0 = bcoef * __ldg(&bias[ncol]);
            const float b1 = bcoef * __ldg(&bias[ncol + 1]);
#pragma unroll
            for (int h = 0; h < 2; h++) {
                const int m = mrow + h * 8;
                const __half h0 = __float2half(alpha * a4[2 * h]     + b0);
                const __half h1 = __float2half(alpha * a4[2 * h + 1] + b1);
                *(__half2*)(O1 + (size_t)m * HD + ncol) = __halves2half2(h0, h1);
            }
        }
    }
}

// ============================================================================
// QK + fused exp epilogue: ph = fp16(exp(Q·K'^T)/16), rowsum += row partials.
// grid (SEQ/BN, SEQ/BM, NB).
// ============================================================================
__global__ __launch_bounds__(NTH, 2)
void mma_qk(const __half* __restrict__ qg, const __half* __restrict__ kg,
            __half* __restrict__ ph, float* __restrict__ rowsum)
{
    extern __shared__ char smem[];
    TileCtx c = make_ctx(smem_u32(smem));

    const int m0 = blockIdx.y * BM;
    const int n0 = blockIdx.x * BN;
    const __half* AH = qg + (size_t)blockIdx.z * SEQ * HD;
    const __half* BH = kg + (size_t)blockIdx.z * SEQ * HD;

    float acc[4][8][4];
    mainloop(c, AH, BH, m0, n0, HD, acc);

    const int rq = c.lane >> 2;
    const int cq = (c.lane & 3) * 2;
    const size_t bO = (size_t)blockIdx.z * SEQ * SEQ;
    float* rs = rowsum + blockIdx.z * SEQ;

#pragma unroll
    for (int mi = 0; mi < 4; mi++) {
#pragma unroll
        for (int h = 0; h < 2; h++) {
            const int mrow = m0 + c.warpM * 64 + mi * 16 + rq + h * 8;
            float rsum = 0.0f;
            __half2 st[8];
#pragma unroll
            for (int ni = 0; ni < 8; ni++) {
                const float e0 = fexp(acc[mi][ni][2 * h]);
                const float e1 = fexp(acc[mi][ni][2 * h + 1]);
                rsum += e0 + e1;
                st[ni] = __halves2half2(__float2half(e0 * PSCALE),
                                        __float2half(e1 * PSCALE));
            }
#pragma unroll
            for (int ni = 0; ni < 8; ni++) {
                const int ncol = n0 + c.warpN * 64 + ni * 8 + cq;
                *(__half2*)(ph + bO + (size_t)mrow * SEQ + ncol) = st[ni];
            }
            // reduce over the 4 lanes sharing this row (lane bits 0-1)
            rsum += __shfl_xor_sync(0xffffffffu, rsum, 1);
            rsum += __shfl_xor_sync(0xffffffffu, rsum, 2);
            if ((c.lane & 3) == 0) atomicAdd(&rs[mrow], rsum);
        }
    }
}

// ============================================================================
// PV + deferred normalization: out = (P_scaled · Vt^T) * 16 / rowsum[row].
// grid (HD/BN, SEQ/BM, NB).
// ============================================================================
__global__ __launch_bounds__(NTH, 2)
void mma_pv(const __half* __restrict__ pg, const __half* __restrict__ vg,
            const float* __restrict__ rowsum, float* __restrict__ out)
{
    extern __shared__ char smem[];
    TileCtx c = make_ctx(smem_u32(smem));

    const int m0 = blockIdx.y * BM;
    const int n0 = blockIdx.x * BN;
    const __half* AH = pg + (size_t)blockIdx.z * SEQ * SEQ;
    const __half* BH = vg + (size_t)blockIdx.z * HD * SEQ;
    float* O = out + (size_t)blockIdx.z * SEQ * HD;
    const float* rs = rowsum + blockIdx.z * SEQ;

    float acc[4][8][4];
    mainloop(c, AH, BH, m0, n0, SEQ, acc);

    const int rq = c.lane >> 2;
    const int cq = (c.lane & 3) * 2;
#pragma unroll
    for (int mi = 0; mi < 4; mi++) {
        const int mrow = m0 + c.warpM * 64 + mi * 16 + rq;
        const float inv0 = 16.0f / __ldg(&rs[mrow]);
        const float inv1 = 16.0f / __ldg(&rs[mrow + 8]);
#pragma unroll
        for (int ni = 0; ni < 8; ni++) {
            const int ncol = n0 + c.warpN * 64 + ni * 8 + cq;
            const float* a4 = acc[mi][ni];
            *(float2*)(O + (size_t)mrow * HD + ncol) =
                make_float2(a4[0] * inv0, a4[1] * inv0);
            *(float2*)(O + (size_t)(mrow + 8) * HD + ncol) =
                make_float2(a4[2] * inv1, a4[3] * inv1);
        }
    }
}

// ============================================================================
// prep kernels
// ============================================================================
// Fused x-prep: reads x and rp ONCE, emits xsh = fp16(x) and xrh = fp16(x+rp).
// First 16 blocks also zero the row-sum buffer (16K floats).
__global__ void prep_x(const float* __restrict__ x, const float* __restrict__ rp,
                       __half* __restrict__ xsh, __half* __restrict__ xrh,
                       float* __restrict__ rs)
{
    const int i = (blockIdx.x * blockDim.x + threadIdx.x) * 4;
    const float4 v = *(const float4*)(x + i);
    const float4 u = *(const float4*)(rp + i);
    *(__half2*)(xsh + i)     = __halves2half2(__float2half(v.x), __float2half(v.y));
    *(__half2*)(xsh + i + 2) = __halves2half2(__float2half(v.z), __float2half(v.w));
    *(__half2*)(xrh + i)     = __halves2half2(__float2half(v.x + u.x),
                                              __float2half(v.y + u.y));
    *(__half2*)(xrh + i + 2) = __halves2half2(__float2half(v.z + u.z),
                                              __float2half(v.w + u.w));
    if (blockIdx.x < 16) {
        const int j = (blockIdx.x * blockDim.x + threadIdx.x) * 4;
        *(float4*)(rs + j) = make_float4(0.f, 0.f, 0.f, 0.f);
    }
}

__global__ void split_w(const float* __restrict__ w0, const float* __restrict__ w1,
                        const float* __restrict__ w2,
                        __half* __restrict__ h0p, __half* __restrict__ h1p,
                        __half* __restrict__ h2p)
{
    const int z = blockIdx.z;
    const float* a = (z == 0) ? w0 : (z == 1) ? w1 : w2;
    __half* hi = (z == 0) ? h0p : (z == 1) ? h1p : h2p;
    const int i = (blockIdx.x * blockDim.x + threadIdx.x) * 4;
    const float4 v = *(const float4*)(a + i);
    *(__half2*)(hi + i)     = __halves2half2(__float2half(v.x), __float2half(v.y));
    *(__half2*)(hi + i + 2) = __halves2half2(__float2half(v.z), __float2half(v.w));
}

// ============================================================================
// kernel_launch
// ============================================================================
extern "C" void kernel_launch(void* const* d_in, const int* in_sizes, int n_in,
                              void* d_out, int out_size)
{
    (void)in_sizes; (void)n_in; (void)out_size;
    const float* x  = (const float*)d_in[0];
    const float* rp = (const float*)d_in[1];
    const float* Wq = (const float*)d_in[2];
    const float* bq = (const float*)d_in[3];
    const float* Wk = (const float*)d_in[4];
    const float* bk = (const float*)d_in[5];
    const float* Wv = (const float*)d_in[6];
    const float* bv = (const float*)d_in[7];
    float* out = (float*)d_out;

    __half *xsh, *xrh, *wqh, *wkh, *wvh;
    __half *qh, *kh, *vth, *ph;
    float* rs;
    cudaGetSymbolAddress((void**)&xsh, g_xsh);
    cudaGetSymbolAddress((void**)&xrh, g_xrh);
    cudaGetSymbolAddress((void**)&wqh, g_wqh);
    cudaGetSymbolAddress((void**)&wkh, g_wkh);
    cudaGetSymbolAddress((void**)&wvh, g_wvh);
    cudaGetSymbolAddress((void**)&qh,  g_qh);
    cudaGetSymbolAddress((void**)&kh,  g_kh);
    cudaGetSymbolAddress((void**)&vth, g_vth);
    cudaGetSymbolAddress((void**)&ph,  g_ph);
    cudaGetSymbolAddress((void**)&rs,  g_rs);

    cudaFuncSetAttribute((const void*)proj3,
                         cudaFuncAttributeMaxDynamicSharedMemorySize, SMEM_GEMM);
    cudaFuncSetAttribute((const void*)mma_qk,
                         cudaFuncAttributeMaxDynamicSharedMemorySize, SMEM_GEMM);
    cudaFuncSetAttribute((const void*)mma_pv,
                         cudaFuncAttributeMaxDynamicSharedMemorySize, SMEM_GEMM);

    const float sc = (float)(1.0 / sqrt((double)HD));

    // --- prep: x/rp read once -> xsh,xrh (+rs zeroing); weight truncation ---
    prep_x<<<TOK * HD / 1024, 256>>>(x, rp, xsh, xrh, rs);
    split_w<<<dim3(HD * HD / 1024, 1, 3), 256>>>(Wq, Wk, Wv, wqh, wkh, wvh);

    // --- fused projections: Q | K' | V(transposed), one launch, 1-MMA ---
    proj3<<<dim3(12, TOK / BM), NTH, SMEM_GEMM>>>(
        xsh, xrh, wqh, wkh, wvh, bq, bk, bv, sc, qh, kh, vth);

    // --- QK with fused exp + row-sum epilogue ---
    mma_qk<<<dim3(SEQ / BN, SEQ / BM, NB), NTH, SMEM_GEMM>>>(qh, kh, ph, rs);

    // --- PV with deferred normalization ---
    mma_pv<<<dim3(HD / BN, SEQ / BM, NB), NTH, SMEM_GEMM>>>(ph, vth, rs, out);
}